// round 1
// baseline (speedup 1.0000x reference)
#include <cuda_runtime.h>
#include <math.h>

// ---------------- problem constants ----------------
#define NS   16384          // samples
#define FF   512            // features
#define BBR  4              // branches (tokens per sample)
#define RTOT (NS*BBR)       // 65536 token rows
#define QKVD 1536
#define HIDD 1024
#define GHID 128
#define SEH  64

// ---------------- scratch (device globals; allocation-free rule) ----------------
__device__ float g_T   [RTOT*FF];    // tokens (r,f)
__device__ float g_x1  [RTOT*FF];    // conv expert
__device__ float g_tA  [RTOT*FF];    // attention stream
__device__ float g_t3  [RTOT*FF];    // mlp stream
__device__ float g_h   [RTOT*FF];    // generic 512-wide scratch
__device__ float g_qkv [RTOT*QKVD];  // qkv (also reused as depthwise scratch)
__device__ float g_hid [RTOT*HIDD];  // ffn/mlp hidden
__device__ float g_se  [NS*FF];      // SE squeeze
__device__ float g_seh [NS*SEH];     // SE hidden
__device__ float g_sesc[NS*FF];      // SE sigmoid scale
__device__ float g_ctx [NS*1024];    // gating context [mean|max]
__device__ float g_gh  [NS*GHID];    // gate hidden
__device__ float g_al  [NS*4];       // alpha (padded to 4)

__device__ __forceinline__ float gelu_f(float x) {
    return 0.5f * x * (1.0f + erff(x * 0.70710678118654752440f));
}

// ---------------- generic SGEMM: C = epi(A[M,K] @ W[N,K]^T + bias [, +Res]) ----------------
// EPI: 0 none, 1 gelu, 2 residual add, 3 scatter to (n, o, b) layout, 4 relu, 5 sigmoid
template<int BM, int BN, int EPI>
__global__ __launch_bounds__(256)
void gemm_k(const float* __restrict__ A, const float* __restrict__ W,
            const float* __restrict__ bias, const float* __restrict__ Res,
            float* __restrict__ C, int M, int N, int K)
{
    constexpr int TM = BM / 16;
    constexpr int TN = BN / 16;
    __shared__ float As[8][BM];
    __shared__ float Ws[8][BN];

    const int bm  = blockIdx.y * BM;
    const int bn  = blockIdx.x * BN;
    const int tid = threadIdx.x;

    const int lr = tid >> 1;
    const int lk = (tid & 1) * 4;
    const bool wload = (tid < BN * 2);

    const float* Ap = A + (size_t)(bm + lr) * K + lk;
    const float* Wp = W + (size_t)(bn + (wload ? lr : 0)) * K + lk;

    const int tm = (tid >> 4) * TM;
    const int tn = (tid & 15) * TN;

    float acc[TM][TN];
#pragma unroll
    for (int i = 0; i < TM; i++)
#pragma unroll
        for (int j = 0; j < TN; j++) acc[i][j] = 0.f;

    float4 av = *(const float4*)Ap;
    float4 wv = wload ? *(const float4*)Wp : make_float4(0.f,0.f,0.f,0.f);

    for (int k0 = 0; k0 < K; k0 += 8) {
        As[lk+0][lr] = av.x; As[lk+1][lr] = av.y; As[lk+2][lr] = av.z; As[lk+3][lr] = av.w;
        if (wload) { Ws[lk+0][lr] = wv.x; Ws[lk+1][lr] = wv.y; Ws[lk+2][lr] = wv.z; Ws[lk+3][lr] = wv.w; }
        __syncthreads();

        if (k0 + 8 < K) {
            Ap += 8; Wp += 8;
            av = *(const float4*)Ap;
            if (wload) wv = *(const float4*)Wp;
        }

#pragma unroll
        for (int kk = 0; kk < 8; kk++) {
            float a[TM], b[TN];
#pragma unroll
            for (int i = 0; i < TM; i += 4) *(float4*)&a[i] = *(const float4*)&As[kk][tm + i];
#pragma unroll
            for (int j = 0; j < TN; j += 4) *(float4*)&b[j] = *(const float4*)&Ws[kk][tn + j];
#pragma unroll
            for (int i = 0; i < TM; i++)
#pragma unroll
                for (int j = 0; j < TN; j++)
                    acc[i][j] = fmaf(a[i], b[j], acc[i][j]);
        }
        __syncthreads();
    }

#pragma unroll
    for (int i = 0; i < TM; i++) {
        const int row = bm + tm + i;
#pragma unroll
        for (int j = 0; j < TN; j++) {
            const int col = bn + tn + j;
            float c = acc[i][j];
            if (bias) c += bias[col];
            if (EPI == 1) c = gelu_f(c);
            else if (EPI == 2) c += Res[(size_t)row * N + col];
            else if (EPI == 4) c = fmaxf(c, 0.f);
            else if (EPI == 5) c = 1.f / (1.f + expf(-c));
            if (EPI == 3) C[(size_t)(row >> 2) * 2048 + col * 4 + (row & 3)] = c;
            else          C[(size_t)row * N + col] = c;
        }
    }
}

// ---------------- transpose (N,F,B)->(r,f) + gating context ----------------
__global__ void transpose_ctx_k(const float* __restrict__ br)
{
    const int n   = blockIdx.x;
    const int f0  = threadIdx.x * 4;   // 128 threads
    const float* src = br + (size_t)n * 2048;
    float4 r0 = *(const float4*)&src[(f0+0)*4];
    float4 r1 = *(const float4*)&src[(f0+1)*4];
    float4 r2 = *(const float4*)&src[(f0+2)*4];
    float4 r3 = *(const float4*)&src[(f0+3)*4];
    float* t = g_T + (size_t)n * 2048;
    *(float4*)&t[0*512 + f0] = make_float4(r0.x, r1.x, r2.x, r3.x);
    *(float4*)&t[1*512 + f0] = make_float4(r0.y, r1.y, r2.y, r3.y);
    *(float4*)&t[2*512 + f0] = make_float4(r0.z, r1.z, r2.z, r3.z);
    *(float4*)&t[3*512 + f0] = make_float4(r0.w, r1.w, r2.w, r3.w);
    float* cx = g_ctx + (size_t)n * 1024;
    float4 mn = make_float4(0.25f*(r0.x+r0.y+r0.z+r0.w), 0.25f*(r1.x+r1.y+r1.z+r1.w),
                            0.25f*(r2.x+r2.y+r2.z+r2.w), 0.25f*(r3.x+r3.y+r3.z+r3.w));
    float4 mx = make_float4(fmaxf(fmaxf(r0.x,r0.y),fmaxf(r0.z,r0.w)),
                            fmaxf(fmaxf(r1.x,r1.y),fmaxf(r1.z,r1.w)),
                            fmaxf(fmaxf(r2.x,r2.y),fmaxf(r2.z,r2.w)),
                            fmaxf(fmaxf(r3.x,r3.y),fmaxf(r3.z,r3.w)));
    *(float4*)&cx[f0]       = mn;
    *(float4*)&cx[512 + f0] = mx;
}

// ---------------- LayerNorm over F=512 (one warp per row) ----------------
__global__ void ln_k(const float* __restrict__ X, const float* __restrict__ w,
                     const float* __restrict__ b, float* __restrict__ Y, int rows)
{
    const int gw   = (int)((blockIdx.x * (size_t)blockDim.x + threadIdx.x) >> 5);
    const int lane = threadIdx.x & 31;
    if (gw >= rows) return;
    const float* x = X + (size_t)gw * FF;
    float4 v[4];
    float s = 0.f, sq = 0.f;
#pragma unroll
    for (int i = 0; i < 4; i++) {
        v[i] = *(const float4*)&x[lane*4 + i*128];
        s  += v[i].x + v[i].y + v[i].z + v[i].w;
        sq += v[i].x*v[i].x + v[i].y*v[i].y + v[i].z*v[i].z + v[i].w*v[i].w;
    }
#pragma unroll
    for (int o = 16; o > 0; o >>= 1) {
        s  += __shfl_xor_sync(~0u, s,  o);
        sq += __shfl_xor_sync(~0u, sq, o);
    }
    const float m   = s  * (1.f/FF);
    const float var = sq * (1.f/FF) - m*m;
    const float rs  = rsqrtf(var + 1e-5f);
    float* y = Y + (size_t)gw * FF;
#pragma unroll
    for (int i = 0; i < 4; i++) {
        const int f = lane*4 + i*128;
        float4 wv = *(const float4*)&w[f];
        float4 bv = *(const float4*)&b[f];
        float4 o4;
        o4.x = (v[i].x - m)*rs*wv.x + bv.x;
        o4.y = (v[i].y - m)*rs*wv.y + bv.y;
        o4.z = (v[i].z - m)*rs*wv.z + bv.z;
        o4.w = (v[i].w - m)*rs*wv.w + bv.w;
        *(float4*)&y[f] = o4;
    }
}

// ---------------- depthwise conv (k=3 over B, pad 1) + SE squeeze ----------------
__global__ void dw_se_k(const float* __restrict__ P, const float* __restrict__ dw)
{
    const int n  = blockIdx.x;
    const int f0 = threadIdx.x * 4;   // 128 threads
    const float* p = P + (size_t)n * 2048;
    float xb[4][4];
    *(float4*)xb[0] = *(const float4*)&p[0*512 + f0];
    *(float4*)xb[1] = *(const float4*)&p[1*512 + f0];
    *(float4*)xb[2] = *(const float4*)&p[2*512 + f0];
    *(float4*)xb[3] = *(const float4*)&p[3*512 + f0];
    float w0[4], w1[4], w2[4];
#pragma unroll
    for (int j = 0; j < 4; j++) {
        w0[j] = dw[(f0+j)*3 + 0];
        w1[j] = dw[(f0+j)*3 + 1];
        w2[j] = dw[(f0+j)*3 + 2];
    }
    float yb[4][4], sm[4];
#pragma unroll
    for (int j = 0; j < 4; j++) {
        yb[0][j] =                    w1[j]*xb[0][j] + w2[j]*xb[1][j];
        yb[1][j] = w0[j]*xb[0][j] + w1[j]*xb[1][j] + w2[j]*xb[2][j];
        yb[2][j] = w0[j]*xb[1][j] + w1[j]*xb[2][j] + w2[j]*xb[3][j];
        yb[3][j] = w0[j]*xb[2][j] + w1[j]*xb[3][j];
        sm[j] = 0.25f*(yb[0][j] + yb[1][j] + yb[2][j] + yb[3][j]);
    }
    float* y = g_qkv + (size_t)n * 2048;   // reuse qkv buffer as dw scratch
#pragma unroll
    for (int b = 0; b < 4; b++) {
        float4 o4 = make_float4(yb[b][0], yb[b][1], yb[b][2], yb[b][3]);
        *(float4*)&y[b*512 + f0] = o4;
    }
    *(float4*)&g_se[(size_t)n*512 + f0] = make_float4(sm[0], sm[1], sm[2], sm[3]);
}

// ---------------- SE-scale + GroupNorm(1 group over F,B) + GELU ----------------
__global__ void gn_k(const float* __restrict__ X, const float* __restrict__ SC,
                     const float* __restrict__ gw, const float* __restrict__ gb,
                     float* __restrict__ Y)
{
    __shared__ float ws[8], wq[8], stats[2];
    const int n = blockIdx.x, tid = threadIdx.x;   // 256 threads
    const float* x  = X  + (size_t)n * 2048;
    const float* sc = SC + (size_t)n * 512;
    float v[8];
    float s = 0.f, sq = 0.f;
#pragma unroll
    for (int i = 0; i < 8; i++) {
        const int e = tid + i*256;
        const float val = x[e] * sc[e & 511];
        v[i] = val; s += val; sq += val*val;
    }
#pragma unroll
    for (int o = 16; o > 0; o >>= 1) {
        s  += __shfl_xor_sync(~0u, s,  o);
        sq += __shfl_xor_sync(~0u, sq, o);
    }
    if ((tid & 31) == 0) { ws[tid >> 5] = s; wq[tid >> 5] = sq; }
    __syncthreads();
    if (tid == 0) {
        float S = 0.f, Q = 0.f;
#pragma unroll
        for (int i = 0; i < 8; i++) { S += ws[i]; Q += wq[i]; }
        const float m = S * (1.f/2048.f);
        stats[0] = m;
        stats[1] = rsqrtf(Q * (1.f/2048.f) - m*m + 1e-5f);
    }
    __syncthreads();
    const float m = stats[0], r = stats[1];
    float* y = Y + (size_t)n * 2048;
#pragma unroll
    for (int i = 0; i < 8; i++) {
        const int e = tid + i*256;
        const int f = e & 511;
        y[e] = gelu_f((v[i] - m) * r * gw[f] + gb[f]);
    }
}

// ---------------- attention core (4 tokens, 4 heads, dh=128); warp = head ----------------
__global__ void attn_k(const float* __restrict__ QKV, float* __restrict__ AO)
{
    const int n     = blockIdx.x;
    const int wid   = threadIdx.x >> 5;   // head (0..3)
    const int lane  = threadIdx.x & 31;
    const int dbase = wid*128 + lane*4;
    const float* base = QKV + (size_t)n * 4 * 1536;
    float4 q[4], k[4], vv[4];
    const float sc = 0.08838834764831845f;   // 128^-0.5
#pragma unroll
    for (int i = 0; i < 4; i++) {
        q[i]  = *(const float4*)&base[i*1536 +        dbase];
        k[i]  = *(const float4*)&base[i*1536 +  512 + dbase];
        vv[i] = *(const float4*)&base[i*1536 + 1024 + dbase];
        q[i].x *= sc; q[i].y *= sc; q[i].z *= sc; q[i].w *= sc;
    }
    float p[4][4];
#pragma unroll
    for (int i = 0; i < 4; i++)
#pragma unroll
        for (int j = 0; j < 4; j++) {
            float d = q[i].x*k[j].x + q[i].y*k[j].y + q[i].z*k[j].z + q[i].w*k[j].w;
#pragma unroll
            for (int o = 16; o > 0; o >>= 1) d += __shfl_xor_sync(~0u, d, o);
            p[i][j] = d;
        }
    float* ao = AO + (size_t)n * 4 * 512;
#pragma unroll
    for (int i = 0; i < 4; i++) {
        const float m  = fmaxf(fmaxf(p[i][0], p[i][1]), fmaxf(p[i][2], p[i][3]));
        const float e0 = expf(p[i][0]-m), e1 = expf(p[i][1]-m);
        const float e2 = expf(p[i][2]-m), e3 = expf(p[i][3]-m);
        const float inv = 1.f / (e0+e1+e2+e3);
        float4 o4;
        o4.x = (e0*vv[0].x + e1*vv[1].x + e2*vv[2].x + e3*vv[3].x) * inv;
        o4.y = (e0*vv[0].y + e1*vv[1].y + e2*vv[2].y + e3*vv[3].y) * inv;
        o4.z = (e0*vv[0].z + e1*vv[1].z + e2*vv[2].z + e3*vv[3].z) * inv;
        o4.w = (e0*vv[0].w + e1*vv[1].w + e2*vv[2].w + e3*vv[3].w) * inv;
        *(float4*)&ao[i*512 + dbase] = o4;
    }
}

// ---------------- gate logits + softmax (warp per sample) ----------------
__global__ void gate2_k(const float* __restrict__ w2, const float* __restrict__ b2)
{
    const int n    = (int)((blockIdx.x * (size_t)blockDim.x + threadIdx.x) >> 5);
    const int lane = threadIdx.x & 31;
    if (n >= NS) return;
    const float* h = g_gh + (size_t)n * 128;
    float lg[3];
#pragma unroll
    for (int e = 0; e < 3; e++) {
        float ps = h[lane]      * w2[e*128 + lane]
                 + h[lane + 32] * w2[e*128 + lane + 32]
                 + h[lane + 64] * w2[e*128 + lane + 64]
                 + h[lane + 96] * w2[e*128 + lane + 96];
#pragma unroll
        for (int o = 16; o > 0; o >>= 1) ps += __shfl_xor_sync(~0u, ps, o);
        lg[e] = ps + b2[e];
    }
    if (lane == 0) {
        const float m  = fmaxf(lg[0], fmaxf(lg[1], lg[2]));
        const float e0 = expf(lg[0]-m), e1 = expf(lg[1]-m), e2 = expf(lg[2]-m);
        const float inv = 1.f / (e0+e1+e2);
        g_al[n*4+0] = e0*inv; g_al[n*4+1] = e1*inv; g_al[n*4+2] = e2*inv;
    }
}

// ---------------- alpha-weighted fusion of the three experts ----------------
__global__ void fuse_k()
{
    const size_t idx = blockIdx.x * (size_t)blockDim.x + threadIdx.x;  // float4 idx
    const int r  = (int)(idx >> 7);
    const int f  = (int)(idx & 127) << 2;
    const int n  = r >> 2;
    const float a0 = g_al[n*4+0], a1 = g_al[n*4+1], a2 = g_al[n*4+2];
    const size_t off = (size_t)r * 512 + f;
    const float4 u = *(const float4*)&g_x1[off];
    const float4 v = *(const float4*)&g_tA[off];
    const float4 w = *(const float4*)&g_t3[off];
    float4 o4;
    o4.x = a0*u.x + a1*v.x + a2*w.x;
    o4.y = a0*u.y + a1*v.y + a2*w.y;
    o4.z = a0*u.z + a1*v.z + a2*w.z;
    o4.w = a0*u.w + a1*v.w + a2*w.w;
    *(float4*)&g_h[off] = o4;
}

// ---------------- launch ----------------
extern "C" void kernel_launch(void* const* d_in, const int* in_sizes, int n_in,
                              void* d_out, int out_size)
{
    (void)in_sizes; (void)n_in; (void)out_size;
    const float* br   = (const float*)d_in[0];
    const float* pw   = (const float*)d_in[1];
    const float* dww  = (const float*)d_in[2];
    const float* gnw  = (const float*)d_in[3];
    const float* gnb  = (const float*)d_in[4];
    const float* sew1 = (const float*)d_in[5];
    const float* sew2 = (const float*)d_in[6];
    const float* lnaw = (const float*)d_in[7];
    const float* lnab = (const float*)d_in[8];
    const float* ipw  = (const float*)d_in[9];
    const float* ipb  = (const float*)d_in[10];
    const float* aow  = (const float*)d_in[11];
    const float* aob  = (const float*)d_in[12];
    const float* lnfw = (const float*)d_in[13];
    const float* lnfb = (const float*)d_in[14];
    const float* f1w  = (const float*)d_in[15];
    const float* f1b  = (const float*)d_in[16];
    const float* f2w  = (const float*)d_in[17];
    const float* f2b  = (const float*)d_in[18];
    const float* mlw  = (const float*)d_in[19];
    const float* mlb  = (const float*)d_in[20];
    const float* m1w  = (const float*)d_in[21];
    const float* m1b  = (const float*)d_in[22];
    const float* m2w  = (const float*)d_in[23];
    const float* m2b  = (const float*)d_in[24];
    const float* g1w  = (const float*)d_in[25];
    const float* g1b  = (const float*)d_in[26];
    const float* g2w  = (const float*)d_in[27];
    const float* g2b  = (const float*)d_in[28];
    const float* opw  = (const float*)d_in[29];
    float* out = (float*)d_out;

    float *pT, *pX1, *pTA, *pT3, *pH, *pQKV, *pHID, *pSE, *pSEH, *pSESC, *pCTX, *pGH;
    cudaGetSymbolAddress((void**)&pT,    g_T);
    cudaGetSymbolAddress((void**)&pX1,   g_x1);
    cudaGetSymbolAddress((void**)&pTA,   g_tA);
    cudaGetSymbolAddress((void**)&pT3,   g_t3);
    cudaGetSymbolAddress((void**)&pH,    g_h);
    cudaGetSymbolAddress((void**)&pQKV,  g_qkv);
    cudaGetSymbolAddress((void**)&pHID,  g_hid);
    cudaGetSymbolAddress((void**)&pSE,   g_se);
    cudaGetSymbolAddress((void**)&pSEH,  g_seh);
    cudaGetSymbolAddress((void**)&pSESC, g_sesc);
    cudaGetSymbolAddress((void**)&pCTX,  g_ctx);
    cudaGetSymbolAddress((void**)&pGH,   g_gh);

    // 1. tokens + gating context
    transpose_ctx_k<<<NS, 128>>>(br);
    // 2. gating MLP + softmax
    gemm_k<128,128,1><<<dim3(1,128),256>>>(pCTX, g1w, g1b, nullptr, pGH, NS, 128, 1024);
    gate2_k<<<NS/8, 256>>>(g2w, g2b);
    // 3. conv expert: pointwise conv
    gemm_k<128,128,0><<<dim3(4,512),256>>>(pT, pw, nullptr, nullptr, pX1, RTOT, 512, 512);
    // 4. depthwise + SE squeeze (dw output into g_qkv scratch)
    dw_se_k<<<NS, 128>>>(pX1, dww);
    // 5. SE MLP
    gemm_k<128,64,4><<<dim3(1,128),256>>>(pSE,  sew1, nullptr, nullptr, pSEH,  NS, 64,  512);
    gemm_k<128,128,5><<<dim3(4,128),256>>>(pSEH, sew2, nullptr, nullptr, pSESC, NS, 512, 64);
    // 6. SE scale + GroupNorm + GELU -> g_x1
    gn_k<<<NS, 256>>>(pQKV, pSESC, gnw, gnb, pX1);
    // 7. attention expert
    ln_k<<<RTOT/8, 256>>>(pT, lnaw, lnab, pH, RTOT);
    gemm_k<128,128,0><<<dim3(12,512),256>>>(pH, ipw, ipb, nullptr, pQKV, RTOT, 1536, 512);
    attn_k<<<NS, 128>>>(pQKV, pH);
    gemm_k<128,128,2><<<dim3(4,512),256>>>(pH, aow, aob, pT, pTA, RTOT, 512, 512);
    ln_k<<<RTOT/8, 256>>>(pTA, lnfw, lnfb, pH, RTOT);
    gemm_k<128,128,1><<<dim3(8,512),256>>>(pH, f1w, f1b, nullptr, pHID, RTOT, 1024, 512);
    gemm_k<128,128,2><<<dim3(4,512),256>>>(pHID, f2w, f2b, pTA, pTA, RTOT, 512, 1024);
    // 8. mlp expert
    ln_k<<<RTOT/8, 256>>>(pT, mlw, mlb, pH, RTOT);
    gemm_k<128,128,1><<<dim3(8,512),256>>>(pH, m1w, m1b, nullptr, pHID, RTOT, 1024, 512);
    gemm_k<128,128,2><<<dim3(4,512),256>>>(pHID, m2w, m2b, pT, pT3, RTOT, 512, 1024);
    // 9. fuse + output projection (scatter to (n, o, b))
    fuse_k<<<RTOT*128/256, 256>>>();
    gemm_k<128,128,3><<<dim3(4,512),256>>>(pH, opw, nullptr, nullptr, out, RTOT, 512, 512);
}

// round 2
// speedup vs baseline: 2.2291x; 2.2291x over previous
#include <cuda_runtime.h>
#include <math.h>
#include <stdint.h>

// ---------------- problem constants ----------------
#define NS   16384          // samples
#define FF   512            // features
#define BBR  4              // branches (tokens per sample)
#define RTOT (NS*BBR)       // 65536 token rows
#define QKVD 1536
#define HIDD 1024
#define GHID 128
#define SEH  64

// ---------------- scratch (device globals; allocation-free rule) ----------------
__device__ float g_T   [RTOT*FF];    // tokens (r,f)
__device__ float g_x1  [RTOT*FF];    // conv expert
__device__ float g_tA  [RTOT*FF];    // attention stream
__device__ float g_t3  [RTOT*FF];    // mlp stream
__device__ float g_h   [RTOT*FF];    // generic 512-wide scratch
__device__ float g_qkv [RTOT*QKVD];  // qkv (also reused as depthwise scratch)
__device__ float g_hid [RTOT*HIDD];  // ffn/mlp hidden
__device__ float g_se  [NS*FF];      // SE squeeze
__device__ float g_seh [NS*SEH];     // SE hidden
__device__ float g_sesc[NS*FF];      // SE sigmoid scale
__device__ float g_ctx [NS*1024];    // gating context [mean|max]
__device__ float g_gh  [NS*GHID];    // gate hidden
__device__ float g_al  [NS*4];       // alpha (padded to 4)

__device__ __forceinline__ float gelu_f(float x) {
    return 0.5f * x * (1.0f + erff(x * 0.70710678118654752440f));
}

__device__ __forceinline__ uint32_t f2tf(float x) {
    uint32_t r;
    asm("cvt.rna.tf32.f32 %0, %1;" : "=r"(r) : "f"(x));
    return r;
}

__device__ __forceinline__ void mma_tf32(float* c, const uint32_t* a, const uint32_t* b) {
    asm volatile(
        "mma.sync.aligned.m16n8k8.row.col.f32.tf32.tf32.f32 "
        "{%0,%1,%2,%3}, {%4,%5,%6,%7}, {%8,%9}, {%0,%1,%2,%3};"
        : "+f"(c[0]), "+f"(c[1]), "+f"(c[2]), "+f"(c[3])
        : "r"(a[0]), "r"(a[1]), "r"(a[2]), "r"(a[3]), "r"(b[0]), "r"(b[1]));
}

// ---------------- TF32 tensor-core GEMM: C = epi(A[M,K] @ W[N,K]^T + bias [,+Res]) ----
// Tile 128x128x16, 8 warps (2x4), warp tile 64x32 (4x4 of m16n8k8).
// EPI: 0 none, 1 gelu, 2 residual add, 3 scatter to (n,o,b), 5 sigmoid
// Requires: M%128==0, N%128==0, K%16==0.
template<int EPI>
__global__ __launch_bounds__(256)
void gemm_tf32(const float* __restrict__ A, const float* __restrict__ W,
               const float* __restrict__ bias, const float* __restrict__ Res,
               float* __restrict__ C, int M, int N, int K)
{
    __shared__ uint32_t As[2][128][20];
    __shared__ uint32_t Ws[2][128][20];

    const int bm  = blockIdx.y * 128;
    const int bn  = blockIdx.x * 128;
    const int tid = threadIdx.x;
    const int wid = tid >> 5;
    const int lane = tid & 31;
    const int wm = wid & 1;        // 0..1  (64-row slab)
    const int wn = wid >> 1;       // 0..3  (32-col slab)
    const int grp = lane >> 2;     // 0..7
    const int tq  = lane & 3;      // 0..3

    // global load mapping: thread -> (row, 8 k's)
    const int lrow = tid >> 1;          // 0..127
    const int lk   = (tid & 1) * 8;     // 0 or 8
    const float* Ap = A + (size_t)(bm + lrow) * K + lk;
    const float* Wp = W + (size_t)(bn + lrow) * K + lk;

    float acc[4][4][4];
#pragma unroll
    for (int i = 0; i < 4; i++)
#pragma unroll
        for (int j = 0; j < 4; j++)
#pragma unroll
            for (int q = 0; q < 4; q++) acc[i][j][q] = 0.f;

    float4 av0 = *(const float4*)Ap;
    float4 av1 = *(const float4*)(Ap + 4);
    float4 wv0 = *(const float4*)Wp;
    float4 wv1 = *(const float4*)(Wp + 4);

    int buf = 0;
    {
        uint32_t* as = &As[0][lrow][lk];
        as[0]=f2tf(av0.x); as[1]=f2tf(av0.y); as[2]=f2tf(av0.z); as[3]=f2tf(av0.w);
        as[4]=f2tf(av1.x); as[5]=f2tf(av1.y); as[6]=f2tf(av1.z); as[7]=f2tf(av1.w);
        uint32_t* ws = &Ws[0][lrow][lk];
        ws[0]=f2tf(wv0.x); ws[1]=f2tf(wv0.y); ws[2]=f2tf(wv0.z); ws[3]=f2tf(wv0.w);
        ws[4]=f2tf(wv1.x); ws[5]=f2tf(wv1.y); ws[6]=f2tf(wv1.z); ws[7]=f2tf(wv1.w);
    }
    __syncthreads();

    for (int k0 = 0; k0 < K; k0 += 16) {
        const bool more = (k0 + 16) < K;
        if (more) {
            Ap += 16; Wp += 16;
            av0 = *(const float4*)Ap;
            av1 = *(const float4*)(Ap + 4);
            wv0 = *(const float4*)Wp;
            wv1 = *(const float4*)(Wp + 4);
        }

        // compute on current buffer
#pragma unroll
        for (int ks = 0; ks < 2; ks++) {
            const int kk = ks * 8 + tq;
            uint32_t af[4][4], bf[4][2];
#pragma unroll
            for (int mt = 0; mt < 4; mt++) {
                const int m = wm * 64 + mt * 16 + grp;
                af[mt][0] = As[buf][m    ][kk];
                af[mt][1] = As[buf][m + 8][kk];
                af[mt][2] = As[buf][m    ][kk + 4];
                af[mt][3] = As[buf][m + 8][kk + 4];
            }
#pragma unroll
            for (int nt = 0; nt < 4; nt++) {
                const int n = wn * 32 + nt * 8 + grp;
                bf[nt][0] = Ws[buf][n][kk];
                bf[nt][1] = Ws[buf][n][kk + 4];
            }
#pragma unroll
            for (int mt = 0; mt < 4; mt++)
#pragma unroll
                for (int nt = 0; nt < 4; nt++)
                    mma_tf32(acc[mt][nt], af[mt], bf[nt]);
        }

        if (more) {
            const int nb = buf ^ 1;
            uint32_t* as = &As[nb][lrow][lk];
            as[0]=f2tf(av0.x); as[1]=f2tf(av0.y); as[2]=f2tf(av0.z); as[3]=f2tf(av0.w);
            as[4]=f2tf(av1.x); as[5]=f2tf(av1.y); as[6]=f2tf(av1.z); as[7]=f2tf(av1.w);
            uint32_t* ws = &Ws[nb][lrow][lk];
            ws[0]=f2tf(wv0.x); ws[1]=f2tf(wv0.y); ws[2]=f2tf(wv0.z); ws[3]=f2tf(wv0.w);
            ws[4]=f2tf(wv1.x); ws[5]=f2tf(wv1.y); ws[6]=f2tf(wv1.z); ws[7]=f2tf(wv1.w);
            __syncthreads();
            buf = nb;
        }
    }

    // ---------------- epilogue ----------------
#pragma unroll
    for (int mt = 0; mt < 4; mt++) {
        const int rbase = bm + wm * 64 + mt * 16 + grp;
#pragma unroll
        for (int nt = 0; nt < 4; nt++) {
            const int col = bn + wn * 32 + nt * 8 + tq * 2;
#pragma unroll
            for (int half = 0; half < 2; half++) {
                const int row = rbase + half * 8;
                float x = acc[mt][nt][half * 2 + 0];
                float y = acc[mt][nt][half * 2 + 1];
                if (bias) { x += bias[col]; y += bias[col + 1]; }
                if (EPI == 1) { x = gelu_f(x); y = gelu_f(y); }
                else if (EPI == 2) {
                    float2 rv = *(const float2*)&Res[(size_t)row * N + col];
                    x += rv.x; y += rv.y;
                }
                else if (EPI == 5) {
                    x = 1.f / (1.f + expf(-x));
                    y = 1.f / (1.f + expf(-y));
                }
                if (EPI == 3) {
                    float* base = C + (size_t)(row >> 2) * 2048 + (row & 3);
                    base[col * 4]       = x;
                    base[(col + 1) * 4] = y;
                } else {
                    *(float2*)&C[(size_t)row * N + col] = make_float2(x, y);
                }
            }
        }
    }
}

// ---------------- legacy fp32 SGEMM (only for SE1: N=64, relu) ----------------
template<int BM, int BN, int EPI>
__global__ __launch_bounds__(256)
void gemm_k(const float* __restrict__ A, const float* __restrict__ W,
            const float* __restrict__ bias, const float* __restrict__ Res,
            float* __restrict__ C, int M, int N, int K)
{
    constexpr int TM = BM / 16;
    constexpr int TN = BN / 16;
    __shared__ float As[8][BM];
    __shared__ float Ws[8][BN];

    const int bm  = blockIdx.y * BM;
    const int bn  = blockIdx.x * BN;
    const int tid = threadIdx.x;

    const int lr = tid >> 1;
    const int lk = (tid & 1) * 4;
    const bool wload = (tid < BN * 2);

    const float* Ap = A + (size_t)(bm + lr) * K + lk;
    const float* Wp = W + (size_t)(bn + (wload ? lr : 0)) * K + lk;

    const int tm = (tid >> 4) * TM;
    const int tn = (tid & 15) * TN;

    float acc[TM][TN];
#pragma unroll
    for (int i = 0; i < TM; i++)
#pragma unroll
        for (int j = 0; j < TN; j++) acc[i][j] = 0.f;

    float4 av = *(const float4*)Ap;
    float4 wv = wload ? *(const float4*)Wp : make_float4(0.f,0.f,0.f,0.f);

    for (int k0 = 0; k0 < K; k0 += 8) {
        As[lk+0][lr] = av.x; As[lk+1][lr] = av.y; As[lk+2][lr] = av.z; As[lk+3][lr] = av.w;
        if (wload) { Ws[lk+0][lr] = wv.x; Ws[lk+1][lr] = wv.y; Ws[lk+2][lr] = wv.z; Ws[lk+3][lr] = wv.w; }
        __syncthreads();

        if (k0 + 8 < K) {
            Ap += 8; Wp += 8;
            av = *(const float4*)Ap;
            if (wload) wv = *(const float4*)Wp;
        }

#pragma unroll
        for (int kk = 0; kk < 8; kk++) {
            float a[TM], b[TN];
#pragma unroll
            for (int i = 0; i < TM; i += 4) *(float4*)&a[i] = *(const float4*)&As[kk][tm + i];
#pragma unroll
            for (int j = 0; j < TN; j += 4) *(float4*)&b[j] = *(const float4*)&Ws[kk][tn + j];
#pragma unroll
            for (int i = 0; i < TM; i++)
#pragma unroll
                for (int j = 0; j < TN; j++)
                    acc[i][j] = fmaf(a[i], b[j], acc[i][j]);
        }
        __syncthreads();
    }

#pragma unroll
    for (int i = 0; i < TM; i++) {
        const int row = bm + tm + i;
#pragma unroll
        for (int j = 0; j < TN; j++) {
            const int col = bn + tn + j;
            float c = acc[i][j];
            if (bias) c += bias[col];
            if (EPI == 1) c = gelu_f(c);
            else if (EPI == 2) c += Res[(size_t)row * N + col];
            else if (EPI == 4) c = fmaxf(c, 0.f);
            else if (EPI == 5) c = 1.f / (1.f + expf(-c));
            if (EPI == 3) C[(size_t)(row >> 2) * 2048 + col * 4 + (row & 3)] = c;
            else          C[(size_t)row * N + col] = c;
        }
    }
}

// ---------------- transpose (N,F,B)->(r,f) + gating context ----------------
__global__ void transpose_ctx_k(const float* __restrict__ br)
{
    const int n   = blockIdx.x;
    const int f0  = threadIdx.x * 4;   // 128 threads
    const float* src = br + (size_t)n * 2048;
    float4 r0 = *(const float4*)&src[(f0+0)*4];
    float4 r1 = *(const float4*)&src[(f0+1)*4];
    float4 r2 = *(const float4*)&src[(f0+2)*4];
    float4 r3 = *(const float4*)&src[(f0+3)*4];
    float* t = g_T + (size_t)n * 2048;
    *(float4*)&t[0*512 + f0] = make_float4(r0.x, r1.x, r2.x, r3.x);
    *(float4*)&t[1*512 + f0] = make_float4(r0.y, r1.y, r2.y, r3.y);
    *(float4*)&t[2*512 + f0] = make_float4(r0.z, r1.z, r2.z, r3.z);
    *(float4*)&t[3*512 + f0] = make_float4(r0.w, r1.w, r2.w, r3.w);
    float* cx = g_ctx + (size_t)n * 1024;
    float4 mn = make_float4(0.25f*(r0.x+r0.y+r0.z+r0.w), 0.25f*(r1.x+r1.y+r1.z+r1.w),
                            0.25f*(r2.x+r2.y+r2.z+r2.w), 0.25f*(r3.x+r3.y+r3.z+r3.w));
    float4 mx = make_float4(fmaxf(fmaxf(r0.x,r0.y),fmaxf(r0.z,r0.w)),
                            fmaxf(fmaxf(r1.x,r1.y),fmaxf(r1.z,r1.w)),
                            fmaxf(fmaxf(r2.x,r2.y),fmaxf(r2.z,r2.w)),
                            fmaxf(fmaxf(r3.x,r3.y),fmaxf(r3.z,r3.w)));
    *(float4*)&cx[f0]       = mn;
    *(float4*)&cx[512 + f0] = mx;
}

// ---------------- LayerNorm over F=512 (one warp per row) ----------------
__global__ void ln_k(const float* __restrict__ X, const float* __restrict__ w,
                     const float* __restrict__ b, float* __restrict__ Y, int rows)
{
    const int gw   = (int)((blockIdx.x * (size_t)blockDim.x + threadIdx.x) >> 5);
    const int lane = threadIdx.x & 31;
    if (gw >= rows) return;
    const float* x = X + (size_t)gw * FF;
    float4 v[4];
    float s = 0.f, sq = 0.f;
#pragma unroll
    for (int i = 0; i < 4; i++) {
        v[i] = *(const float4*)&x[lane*4 + i*128];
        s  += v[i].x + v[i].y + v[i].z + v[i].w;
        sq += v[i].x*v[i].x + v[i].y*v[i].y + v[i].z*v[i].z + v[i].w*v[i].w;
    }
#pragma unroll
    for (int o = 16; o > 0; o >>= 1) {
        s  += __shfl_xor_sync(~0u, s,  o);
        sq += __shfl_xor_sync(~0u, sq, o);
    }
    const float m   = s  * (1.f/FF);
    const float var = sq * (1.f/FF) - m*m;
    const float rs  = rsqrtf(var + 1e-5f);
    float* y = Y + (size_t)gw * FF;
#pragma unroll
    for (int i = 0; i < 4; i++) {
        const int f = lane*4 + i*128;
        float4 wv = *(const float4*)&w[f];
        float4 bv = *(const float4*)&b[f];
        float4 o4;
        o4.x = (v[i].x - m)*rs*wv.x + bv.x;
        o4.y = (v[i].y - m)*rs*wv.y + bv.y;
        o4.z = (v[i].z - m)*rs*wv.z + bv.z;
        o4.w = (v[i].w - m)*rs*wv.w + bv.w;
        *(float4*)&y[f] = o4;
    }
}

// ---------------- depthwise conv (k=3 over B, pad 1) + SE squeeze ----------------
__global__ void dw_se_k(const float* __restrict__ P, const float* __restrict__ dw)
{
    const int n  = blockIdx.x;
    const int f0 = threadIdx.x * 4;   // 128 threads
    const float* p = P + (size_t)n * 2048;
    float xb[4][4];
    *(float4*)xb[0] = *(const float4*)&p[0*512 + f0];
    *(float4*)xb[1] = *(const float4*)&p[1*512 + f0];
    *(float4*)xb[2] = *(const float4*)&p[2*512 + f0];
    *(float4*)xb[3] = *(const float4*)&p[3*512 + f0];
    float w0[4], w1[4], w2[4];
#pragma unroll
    for (int j = 0; j < 4; j++) {
        w0[j] = dw[(f0+j)*3 + 0];
        w1[j] = dw[(f0+j)*3 + 1];
        w2[j] = dw[(f0+j)*3 + 2];
    }
    float yb[4][4], sm[4];
#pragma unroll
    for (int j = 0; j < 4; j++) {
        yb[0][j] =                    w1[j]*xb[0][j] + w2[j]*xb[1][j];
        yb[1][j] = w0[j]*xb[0][j] + w1[j]*xb[1][j] + w2[j]*xb[2][j];
        yb[2][j] = w0[j]*xb[1][j] + w1[j]*xb[2][j] + w2[j]*xb[3][j];
        yb[3][j] = w0[j]*xb[2][j] + w1[j]*xb[3][j];
        sm[j] = 0.25f*(yb[0][j] + yb[1][j] + yb[2][j] + yb[3][j]);
    }
    float* y = g_qkv + (size_t)n * 2048;   // reuse qkv buffer as dw scratch
#pragma unroll
    for (int b = 0; b < 4; b++) {
        float4 o4 = make_float4(yb[b][0], yb[b][1], yb[b][2], yb[b][3]);
        *(float4*)&y[b*512 + f0] = o4;
    }
    *(float4*)&g_se[(size_t)n*512 + f0] = make_float4(sm[0], sm[1], sm[2], sm[3]);
}

// ---------------- SE-scale + GroupNorm(1 group over F,B) + GELU ----------------
__global__ void gn_k(const float* __restrict__ X, const float* __restrict__ SC,
                     const float* __restrict__ gw, const float* __restrict__ gb,
                     float* __restrict__ Y)
{
    __shared__ float ws[8], wq[8], stats[2];
    const int n = blockIdx.x, tid = threadIdx.x;   // 256 threads
    const float* x  = X  + (size_t)n * 2048;
    const float* sc = SC + (size_t)n * 512;
    float v[8];
    float s = 0.f, sq = 0.f;
#pragma unroll
    for (int i = 0; i < 8; i++) {
        const int e = tid + i*256;
        const float val = x[e] * sc[e & 511];
        v[i] = val; s += val; sq += val*val;
    }
#pragma unroll
    for (int o = 16; o > 0; o >>= 1) {
        s  += __shfl_xor_sync(~0u, s,  o);
        sq += __shfl_xor_sync(~0u, sq, o);
    }
    if ((tid & 31) == 0) { ws[tid >> 5] = s; wq[tid >> 5] = sq; }
    __syncthreads();
    if (tid == 0) {
        float S = 0.f, Q = 0.f;
#pragma unroll
        for (int i = 0; i < 8; i++) { S += ws[i]; Q += wq[i]; }
        const float m = S * (1.f/2048.f);
        stats[0] = m;
        stats[1] = rsqrtf(Q * (1.f/2048.f) - m*m + 1e-5f);
    }
    __syncthreads();
    const float m = stats[0], r = stats[1];
    float* y = Y + (size_t)n * 2048;
#pragma unroll
    for (int i = 0; i < 8; i++) {
        const int e = tid + i*256;
        const int f = e & 511;
        y[e] = gelu_f((v[i] - m) * r * gw[f] + gb[f]);
    }
}

// ---------------- attention core (4 tokens, 4 heads, dh=128); warp = head ----------------
__global__ void attn_k(const float* __restrict__ QKV, float* __restrict__ AO)
{
    const int n     = blockIdx.x;
    const int wid   = threadIdx.x >> 5;   // head (0..3)
    const int lane  = threadIdx.x & 31;
    const int dbase = wid*128 + lane*4;
    const float* base = QKV + (size_t)n * 4 * 1536;
    float4 q[4], k[4], vv[4];
    const float sc = 0.08838834764831845f;   // 128^-0.5
#pragma unroll
    for (int i = 0; i < 4; i++) {
        q[i]  = *(const float4*)&base[i*1536 +        dbase];
        k[i]  = *(const float4*)&base[i*1536 +  512 + dbase];
        vv[i] = *(const float4*)&base[i*1536 + 1024 + dbase];
        q[i].x *= sc; q[i].y *= sc; q[i].z *= sc; q[i].w *= sc;
    }
    float p[4][4];
#pragma unroll
    for (int i = 0; i < 4; i++)
#pragma unroll
        for (int j = 0; j < 4; j++) {
            float d = q[i].x*k[j].x + q[i].y*k[j].y + q[i].z*k[j].z + q[i].w*k[j].w;
#pragma unroll
            for (int o = 16; o > 0; o >>= 1) d += __shfl_xor_sync(~0u, d, o);
            p[i][j] = d;
        }
    float* ao = AO + (size_t)n * 4 * 512;
#pragma unroll
    for (int i = 0; i < 4; i++) {
        const float m  = fmaxf(fmaxf(p[i][0], p[i][1]), fmaxf(p[i][2], p[i][3]));
        const float e0 = expf(p[i][0]-m), e1 = expf(p[i][1]-m);
        const float e2 = expf(p[i][2]-m), e3 = expf(p[i][3]-m);
        const float inv = 1.f / (e0+e1+e2+e3);
        float4 o4;
        o4.x = (e0*vv[0].x + e1*vv[1].x + e2*vv[2].x + e3*vv[3].x) * inv;
        o4.y = (e0*vv[0].y + e1*vv[1].y + e2*vv[2].y + e3*vv[3].y) * inv;
        o4.z = (e0*vv[0].z + e1*vv[1].z + e2*vv[2].z + e3*vv[3].z) * inv;
        o4.w = (e0*vv[0].w + e1*vv[1].w + e2*vv[2].w + e3*vv[3].w) * inv;
        *(float4*)&ao[i*512 + dbase] = o4;
    }
}

// ---------------- gate logits + softmax (warp per sample) ----------------
__global__ void gate2_k(const float* __restrict__ w2, const float* __restrict__ b2)
{
    const int n    = (int)((blockIdx.x * (size_t)blockDim.x + threadIdx.x) >> 5);
    const int lane = threadIdx.x & 31;
    if (n >= NS) return;
    const float* h = g_gh + (size_t)n * 128;
    float lg[3];
#pragma unroll
    for (int e = 0; e < 3; e++) {
        float ps = h[lane]      * w2[e*128 + lane]
                 + h[lane + 32] * w2[e*128 + lane + 32]
                 + h[lane + 64] * w2[e*128 + lane + 64]
                 + h[lane + 96] * w2[e*128 + lane + 96];
#pragma unroll
        for (int o = 16; o > 0; o >>= 1) ps += __shfl_xor_sync(~0u, ps, o);
        lg[e] = ps + b2[e];
    }
    if (lane == 0) {
        const float m  = fmaxf(lg[0], fmaxf(lg[1], lg[2]));
        const float e0 = expf(lg[0]-m), e1 = expf(lg[1]-m), e2 = expf(lg[2]-m);
        const float inv = 1.f / (e0+e1+e2);
        g_al[n*4+0] = e0*inv; g_al[n*4+1] = e1*inv; g_al[n*4+2] = e2*inv;
    }
}

// ---------------- alpha-weighted fusion of the three experts ----------------
__global__ void fuse_k()
{
    const size_t idx = blockIdx.x * (size_t)blockDim.x + threadIdx.x;  // float4 idx
    const int r  = (int)(idx >> 7);
    const int f  = (int)(idx & 127) << 2;
    const int n  = r >> 2;
    const float a0 = g_al[n*4+0], a1 = g_al[n*4+1], a2 = g_al[n*4+2];
    const size_t off = (size_t)r * 512 + f;
    const float4 u = *(const float4*)&g_x1[off];
    const float4 v = *(const float4*)&g_tA[off];
    const float4 w = *(const float4*)&g_t3[off];
    float4 o4;
    o4.x = a0*u.x + a1*v.x + a2*w.x;
    o4.y = a0*u.y + a1*v.y + a2*w.y;
    o4.z = a0*u.z + a1*v.z + a2*w.z;
    o4.w = a0*u.w + a1*v.w + a2*w.w;
    *(float4*)&g_h[off] = o4;
}

// ---------------- launch ----------------
extern "C" void kernel_launch(void* const* d_in, const int* in_sizes, int n_in,
                              void* d_out, int out_size)
{
    (void)in_sizes; (void)n_in; (void)out_size;
    const float* br   = (const float*)d_in[0];
    const float* pw   = (const float*)d_in[1];
    const float* dww  = (const float*)d_in[2];
    const float* gnw  = (const float*)d_in[3];
    const float* gnb  = (const float*)d_in[4];
    const float* sew1 = (const float*)d_in[5];
    const float* sew2 = (const float*)d_in[6];
    const float* lnaw = (const float*)d_in[7];
    const float* lnab = (const float*)d_in[8];
    const float* ipw  = (const float*)d_in[9];
    const float* ipb  = (const float*)d_in[10];
    const float* aow  = (const float*)d_in[11];
    const float* aob  = (const float*)d_in[12];
    const float* lnfw = (const float*)d_in[13];
    const float* lnfb = (const float*)d_in[14];
    const float* f1w  = (const float*)d_in[15];
    const float* f1b  = (const float*)d_in[16];
    const float* f2w  = (const float*)d_in[17];
    const float* f2b  = (const float*)d_in[18];
    const float* mlw  = (const float*)d_in[19];
    const float* mlb  = (const float*)d_in[20];
    const float* m1w  = (const float*)d_in[21];
    const float* m1b  = (const float*)d_in[22];
    const float* m2w  = (const float*)d_in[23];
    const float* m2b  = (const float*)d_in[24];
    const float* g1w  = (const float*)d_in[25];
    const float* g1b  = (const float*)d_in[26];
    const float* g2w  = (const float*)d_in[27];
    const float* g2b  = (const float*)d_in[28];
    const float* opw  = (const float*)d_in[29];
    float* out = (float*)d_out;

    float *pT, *pX1, *pTA, *pT3, *pH, *pQKV, *pHID, *pSE, *pSEH, *pSESC, *pCTX, *pGH;
    cudaGetSymbolAddress((void**)&pT,    g_T);
    cudaGetSymbolAddress((void**)&pX1,   g_x1);
    cudaGetSymbolAddress((void**)&pTA,   g_tA);
    cudaGetSymbolAddress((void**)&pT3,   g_t3);
    cudaGetSymbolAddress((void**)&pH,    g_h);
    cudaGetSymbolAddress((void**)&pQKV,  g_qkv);
    cudaGetSymbolAddress((void**)&pHID,  g_hid);
    cudaGetSymbolAddress((void**)&pSE,   g_se);
    cudaGetSymbolAddress((void**)&pSEH,  g_seh);
    cudaGetSymbolAddress((void**)&pSESC, g_sesc);
    cudaGetSymbolAddress((void**)&pCTX,  g_ctx);
    cudaGetSymbolAddress((void**)&pGH,   g_gh);

    // 1. tokens + gating context
    transpose_ctx_k<<<NS, 128>>>(br);
    // 2. gating MLP + softmax
    gemm_tf32<1><<<dim3(1,128),256>>>(pCTX, g1w, g1b, nullptr, pGH, NS, 128, 1024);
    gate2_k<<<NS/8, 256>>>(g2w, g2b);
    // 3. conv expert: pointwise conv
    gemm_tf32<0><<<dim3(4,512),256>>>(pT, pw, nullptr, nullptr, pX1, RTOT, 512, 512);
    // 4. depthwise + SE squeeze (dw output into g_qkv scratch)
    dw_se_k<<<NS, 128>>>(pX1, dww);
    // 5. SE MLP
    gemm_k<128,64,4><<<dim3(1,128),256>>>(pSE,  sew1, nullptr, nullptr, pSEH,  NS, 64,  512);
    gemm_tf32<5><<<dim3(4,128),256>>>(pSEH, sew2, nullptr, nullptr, pSESC, NS, 512, 64);
    // 6. SE scale + GroupNorm + GELU -> g_x1
    gn_k<<<NS, 256>>>(pQKV, pSESC, gnw, gnb, pX1);
    // 7. attention expert
    ln_k<<<RTOT/8, 256>>>(pT, lnaw, lnab, pH, RTOT);
    gemm_tf32<0><<<dim3(12,512),256>>>(pH, ipw, ipb, nullptr, pQKV, RTOT, 1536, 512);
    attn_k<<<NS, 128>>>(pQKV, pH);
    gemm_tf32<2><<<dim3(4,512),256>>>(pH, aow, aob, pT, pTA, RTOT, 512, 512);
    ln_k<<<RTOT/8, 256>>>(pTA, lnfw, lnfb, pH, RTOT);
    gemm_tf32<1><<<dim3(8,512),256>>>(pH, f1w, f1b, nullptr, pHID, RTOT, 1024, 512);
    gemm_tf32<2><<<dim3(4,512),256>>>(pHID, f2w, f2b, pTA, pTA, RTOT, 512, 1024);
    // 8. mlp expert
    ln_k<<<RTOT/8, 256>>>(pT, mlw, mlb, pH, RTOT);
    gemm_tf32<1><<<dim3(8,512),256>>>(pH, m1w, m1b, nullptr, pHID, RTOT, 1024, 512);
    gemm_tf32<2><<<dim3(4,512),256>>>(pHID, m2w, m2b, pT, pT3, RTOT, 512, 1024);
    // 9. fuse + output projection (scatter to (n, o, b))
    fuse_k<<<RTOT*128/256, 256>>>();
    gemm_tf32<3><<<dim3(4,512),256>>>(pH, opw, nullptr, nullptr, out, RTOT, 512, 512);
}